// round 2
// baseline (speedup 1.0000x reference)
#include <cuda_runtime.h>
#include <cuda_bf16.h>
#include <cstdint>

// Problem constants
#define NB    4
#define LSEQ  2048
#define HH    16
#define DD    32
#define DIMM  512
#define MROWS (NB*LSEQ)      // 8192
#define TCH   128            // chunk length
#define CCH   (LSEQ/TCH)     // 16 chunks

// ---------------- scratch (device globals; no allocations) ----------------
__device__ float g_Q[(size_t)MROWS*DIMM];   // softmax(query @ Wq^T)
__device__ float g_K[(size_t)MROWS*DIMM];   // softmax(key   @ Wk^T)
__device__ float g_V[(size_t)MROWS*DIMM];   // key @ Wv^T
__device__ float g_CS[(size_t)NB*HH*CCH*DD*DD]; // per-chunk K^T V sums
__device__ float g_S0[(size_t)NB*HH*CCH*DD*DD]; // exclusive prefix states

// ---------------- Kernel 1: projections Y = X @ W^T -----------------------
// X: (MROWS, 512) row-major. W: (512, 512) row-major (out-dim major, k minor).
// Tiled 64x64x16, 256 threads, 4x4 register tiles.
__global__ __launch_bounds__(256) void proj_gemm(
    const float* __restrict__ query, const float* __restrict__ key,
    const float* __restrict__ Wq, const float* __restrict__ Wk,
    const float* __restrict__ Wv)
{
    __shared__ float As[16][64];  // As[k][m] = X[m0+m][k0+k]
    __shared__ float Bs[16][64];  // Bs[k][n] = W[n0+n][k0+k]

    const int bz = blockIdx.z;
    const float* X = (bz == 0) ? query : key;
    const float* W = (bz == 0) ? Wq : (bz == 1 ? Wk : Wv);
    float* Y = (bz == 0) ? g_Q : (bz == 1 ? g_K : g_V);

    const int m0 = blockIdx.y * 64;
    const int n0 = blockIdx.x * 64;
    const int tid = threadIdx.x;
    const int tx = tid & 15, ty = tid >> 4;
    const int lm = tid & 63, lk4 = tid >> 6;   // loader: row within tile, k-quad

    float acc[4][4] = {};

    for (int k0 = 0; k0 < DIMM; k0 += 16) {
        float4 xa = *(const float4*)&X[(size_t)(m0 + lm) * DIMM + k0 + lk4 * 4];
        float4 wb = *(const float4*)&W[(size_t)(n0 + lm) * DIMM + k0 + lk4 * 4];
        As[lk4*4+0][lm] = xa.x; As[lk4*4+1][lm] = xa.y;
        As[lk4*4+2][lm] = xa.z; As[lk4*4+3][lm] = xa.w;
        Bs[lk4*4+0][lm] = wb.x; Bs[lk4*4+1][lm] = wb.y;
        Bs[lk4*4+2][lm] = wb.z; Bs[lk4*4+3][lm] = wb.w;
        __syncthreads();
        #pragma unroll
        for (int kk = 0; kk < 16; kk++) {
            float a[4], b[4];
            *(float4*)a = *(const float4*)&As[kk][ty * 4];
            *(float4*)b = *(const float4*)&Bs[kk][tx * 4];
            #pragma unroll
            for (int i = 0; i < 4; i++)
                #pragma unroll
                for (int j = 0; j < 4; j++)
                    acc[i][j] = fmaf(a[i], b[j], acc[i][j]);
        }
        __syncthreads();
    }

    #pragma unroll
    for (int i = 0; i < 4; i++) {
        float4 o = make_float4(acc[i][0], acc[i][1], acc[i][2], acc[i][3]);
        *(float4*)&Y[(size_t)(m0 + ty * 4 + i) * DIMM + n0 + tx * 4] = o;
    }
}

// ---------------- Kernel 2: softmax over groups of 32 (in-place Q, K) -----
__global__ __launch_bounds__(256) void softmax32()
{
    const int total = MROWS * HH;  // groups per buffer
    int g = blockIdx.x * 8 + (threadIdx.x >> 5);
    const int lane = threadIdx.x & 31;
    float* buf = g_Q;
    if (g >= total) { buf = g_K; g -= total; }
    if (g >= total) return;

    float x = buf[(size_t)g * 32 + lane];
    float mx = x;
    #pragma unroll
    for (int o = 16; o; o >>= 1) mx = fmaxf(mx, __shfl_xor_sync(~0u, mx, o));
    float e = __expf(x - mx);
    float s = e;
    #pragma unroll
    for (int o = 16; o; o >>= 1) s += __shfl_xor_sync(~0u, s, o);
    buf[(size_t)g * 32 + lane] = e / s;
}

// ---------------- Kernel 3: per-chunk sums  CS = K_chunk^T @ V_chunk ------
__global__ __launch_bounds__(256) void chunk_sum()
{
    __shared__ float Ks[TCH][36];
    __shared__ float Vs[TCH][36];
    const int c = blockIdx.x, h = blockIdx.y, n = blockIdx.z;
    const size_t base = ((size_t)(n * LSEQ + c * TCH)) * DIMM + h * DD;
    const int tid = threadIdx.x;

    #pragma unroll
    for (int r = 0; r < 4; r++) {
        int fidx = tid + r * 256;
        int t = fidx >> 3, dq = fidx & 7;
        *(float4*)&Ks[t][dq*4] = *(const float4*)&g_K[base + (size_t)t * DIMM + dq * 4];
        *(float4*)&Vs[t][dq*4] = *(const float4*)&g_V[base + (size_t)t * DIMM + dq * 4];
    }
    __syncthreads();

    const int d = tid >> 3, e0 = (tid & 7) * 4;
    float a0 = 0.f, a1 = 0.f, a2 = 0.f, a3 = 0.f;
    #pragma unroll 4
    for (int t = 0; t < TCH; t++) {
        float kd = Ks[t][d];
        float4 v = *(const float4*)&Vs[t][e0];
        a0 = fmaf(kd, v.x, a0); a1 = fmaf(kd, v.y, a1);
        a2 = fmaf(kd, v.z, a2); a3 = fmaf(kd, v.w, a3);
    }
    size_t outp = ((size_t)((n * HH + h) * CCH + c)) * 1024 + d * 32 + e0;
    *(float4*)&g_CS[outp] = make_float4(a0, a1, a2, a3);
}

// ---------------- Kernel 4: exclusive prefix over chunks ------------------
__global__ __launch_bounds__(1024) void prefix_state()
{
    const int bh = blockIdx.x;       // (n*H + h), 64 blocks
    const int tid = threadIdx.x;     // 1024 = D*D elements
    float acc = 0.f;
    size_t base = (size_t)bh * CCH * 1024 + tid;
    #pragma unroll
    for (int c = 0; c < CCH; c++) {
        g_S0[base + (size_t)c * 1024] = acc;
        acc += g_CS[base + (size_t)c * 1024];
    }
}

// ---------------- Kernel 5: intra-chunk causal attention ------------------
// out[i][e] = sum_d Q[i][d]*S0[d][e]  +  sum_{j<=i} (Q_i . K_j) * V[j][e]
// 256 threads: A tile 8x8 per thread with i = ty + 16*ii, j = tx + 16*jj.
#define ATTN_SMEM_FLOATS (36*128*3 + 36*32 + 132*128)
__global__ __launch_bounds__(256) void chunk_attn(float* __restrict__ out)
{
    extern __shared__ float sm[];
    float (*Qs)[36]  = (float(*)[36])(sm);
    float (*Ks)[36]  = (float(*)[36])(sm + 4608);
    float (*Vs)[36]  = (float(*)[36])(sm + 9216);
    float (*S0)[36]  = (float(*)[36])(sm + 13824);
    float (*As)[132] = (float(*)[132])(sm + 14976);

    const int c = blockIdx.x, h = blockIdx.y, n = blockIdx.z;
    const int tid = threadIdx.x;
    const int tx = tid & 15, ty = tid >> 4;
    const size_t base = ((size_t)(n * LSEQ + c * TCH)) * DIMM + h * DD;

    #pragma unroll
    for (int r = 0; r < 4; r++) {
        int fidx = tid + r * 256;
        int t = fidx >> 3, dq = fidx & 7;
        size_t g = base + (size_t)t * DIMM + dq * 4;
        *(float4*)&Qs[t][dq*4] = *(const float4*)&g_Q[g];
        *(float4*)&Ks[t][dq*4] = *(const float4*)&g_K[g];
        *(float4*)&Vs[t][dq*4] = *(const float4*)&g_V[g];
    }
    {
        size_t sbase = ((size_t)((n * HH + h) * CCH + c)) * 1024;
        float4 s = *(const float4*)&g_S0[sbase + (size_t)tid * 4];
        int d = (tid * 4) >> 5, e = (tid * 4) & 31;
        *(float4*)&S0[d][e] = s;
    }
    __syncthreads();

    // Phase A: A[i][j] = Q_i . K_j  (D=32 inner), causal mask j<=i
    float acc[8][8] = {};
    #pragma unroll
    for (int dq = 0; dq < 8; dq++) {
        float4 kq[8];
        #pragma unroll
        for (int jj = 0; jj < 8; jj++)
            kq[jj] = *(const float4*)&Ks[tx + jj * 16][dq * 4];
        #pragma unroll
        for (int ii = 0; ii < 8; ii++) {
            float4 q = *(const float4*)&Qs[ty + ii * 16][dq * 4];
            #pragma unroll
            for (int jj = 0; jj < 8; jj++) {
                acc[ii][jj] = fmaf(q.x, kq[jj].x, acc[ii][jj]);
                acc[ii][jj] = fmaf(q.y, kq[jj].y, acc[ii][jj]);
                acc[ii][jj] = fmaf(q.z, kq[jj].z, acc[ii][jj]);
                acc[ii][jj] = fmaf(q.w, kq[jj].w, acc[ii][jj]);
            }
        }
    }
    #pragma unroll
    for (int ii = 0; ii < 8; ii++) {
        int i = ty + ii * 16;
        #pragma unroll
        for (int jj = 0; jj < 8; jj++) {
            int j = tx + jj * 16;
            As[i][j] = (j <= i) ? acc[ii][jj] : 0.0f;
        }
    }
    __syncthreads();

    // Phase B: out = Q @ S0 + A @ V ;  i = ty + 16*ii (8 rows), e = 2*tx (2 cols)
    float o0[8] = {}, o1[8] = {};
    #pragma unroll 4
    for (int d = 0; d < 32; d++) {
        float s0 = S0[d][tx * 2], s1 = S0[d][tx * 2 + 1];
        #pragma unroll
        for (int ii = 0; ii < 8; ii++) {
            float q = Qs[ty + ii * 16][d];
            o0[ii] = fmaf(q, s0, o0[ii]);
            o1[ii] = fmaf(q, s1, o1[ii]);
        }
    }
    #pragma unroll 4
    for (int j = 0; j < TCH; j++) {
        float v0 = Vs[j][tx * 2], v1 = Vs[j][tx * 2 + 1];
        #pragma unroll
        for (int ii = 0; ii < 8; ii++) {
            float a = As[ty + ii * 16][j];
            o0[ii] = fmaf(a, v0, o0[ii]);
            o1[ii] = fmaf(a, v1, o1[ii]);
        }
    }
    #pragma unroll
    for (int ii = 0; ii < 8; ii++) {
        int i = ty + ii * 16;
        *(float2*)&out[base + (size_t)i * DIMM + tx * 2] = make_float2(o0[ii], o1[ii]);
    }
}

// ---------------- launch ---------------------------------------------------
extern "C" void kernel_launch(void* const* d_in, const int* in_sizes, int n_in,
                              void* d_out, int out_size)
{
    const float* query = (const float*)d_in[0];
    const float* key   = (const float*)d_in[1];
    const float* Wq    = (const float*)d_in[2];
    const float* Wk    = (const float*)d_in[3];
    const float* Wv    = (const float*)d_in[4];
    float* out = (float*)d_out;

    cudaFuncSetAttribute(chunk_attn, cudaFuncAttributeMaxDynamicSharedMemorySize,
                         ATTN_SMEM_FLOATS * (int)sizeof(float));

    // 1) three projections
    proj_gemm<<<dim3(DIMM / 64, MROWS / 64, 3), 256>>>(query, key, Wq, Wk, Wv);
    // 2) softmax over D=32 for Q and K (in place) — 262144 groups, 8 per block
    softmax32<<<(2 * MROWS * HH) / 8, 256>>>();
    // 3) per-chunk K^T V sums
    chunk_sum<<<dim3(CCH, HH, NB), 256>>>();
    // 4) exclusive prefix of chunk states
    prefix_state<<<NB * HH, 1024>>>();
    // 5) intra-chunk causal attention + output
    chunk_attn<<<dim3(CCH, HH, NB), 256, ATTN_SMEM_FLOATS * (int)sizeof(float)>>>(out);
}

// round 4
// speedup vs baseline: 2.4375x; 2.4375x over previous
#include <cuda_runtime.h>
#include <cuda_bf16.h>
#include <cstdint>

// Problem constants
#define NB    4
#define LSEQ  2048
#define HH    16
#define DD    32
#define DIMM  512
#define MROWS (NB*LSEQ)      // 8192
#define TCH   128            // chunk length
#define CCH   (LSEQ/TCH)     // 16 chunks

// ---------------- scratch (device globals; no allocations) ----------------
__device__ float g_Q[(size_t)MROWS*DIMM];
__device__ float g_K[(size_t)MROWS*DIMM];
__device__ float g_V[(size_t)MROWS*DIMM];
__device__ float g_CS[(size_t)NB*HH*CCH*DD*DD];
__device__ float g_S0[(size_t)NB*HH*CCH*DD*DD];
__device__ __nv_bfloat16 g_Xhi[(size_t)2*MROWS*DIMM];  // query rows then key rows
__device__ __nv_bfloat16 g_Xlo[(size_t)2*MROWS*DIMM];
__device__ __nv_bfloat16 g_Whi[(size_t)3*DIMM*DIMM];   // Wq, Wk, Wv
__device__ __nv_bfloat16 g_Wlo[(size_t)3*DIMM*DIMM];

// ---------------- PTX helpers (sm_80+ legacy tensor path) ------------------
__device__ __forceinline__ void ldmx4(uint32_t addr, uint32_t* r) {
    asm volatile("ldmatrix.sync.aligned.m8n8.x4.shared.b16 {%0,%1,%2,%3}, [%4];"
        : "=r"(r[0]), "=r"(r[1]), "=r"(r[2]), "=r"(r[3]) : "r"(addr));
}
__device__ __forceinline__ void mma16816(float* d, const uint32_t* a, const uint32_t* b) {
    asm volatile("mma.sync.aligned.m16n8k16.row.col.f32.bf16.bf16.f32 "
        "{%0,%1,%2,%3}, {%4,%5,%6,%7}, {%8,%9}, {%0,%1,%2,%3};"
        : "+f"(d[0]), "+f"(d[1]), "+f"(d[2]), "+f"(d[3])
        : "r"(a[0]), "r"(a[1]), "r"(a[2]), "r"(a[3]), "r"(b[0]), "r"(b[1]));
}
__device__ __forceinline__ void cp_async16(uint32_t dst, const void* src) {
    asm volatile("cp.async.cg.shared.global [%0], [%1], 16;" :: "r"(dst), "l"(src) : "memory");
}
#define CP_COMMIT()  asm volatile("cp.async.commit_group;" ::: "memory")
#define CP_WAIT(n)   asm volatile("cp.async.wait_group %0;" :: "n"(n) : "memory")
#define SW128(off)   ((off) ^ (((off) >> 3) & 0x70u))

// ---------------- Kernel 0: fp32 -> bf16 hi/lo split -----------------------
__global__ __launch_bounds__(256) void split_bf16(
    const float* __restrict__ query, const float* __restrict__ key,
    const float* __restrict__ Wq, const float* __restrict__ Wk,
    const float* __restrict__ Wv)
{
    const size_t XQ = (size_t)2 * MROWS * DIMM / 4;   // quads in X
    const size_t WQ = (size_t)DIMM * DIMM / 4;        // quads per W
    size_t qi = (size_t)blockIdx.x * 256 + threadIdx.x;
    const float* src; __nv_bfloat16 *hi, *lo; size_t si;
    if (qi < XQ) {
        size_t half = XQ / 2;
        src = (qi < half) ? query : key;
        si = (qi < half) ? qi : qi - half;
        hi = g_Xhi + qi * 4; lo = g_Xlo + qi * 4;
    } else {
        size_t wi = qi - XQ;
        if (wi >= 3 * WQ) return;
        int w = (int)(wi / WQ);
        src = (w == 0) ? Wq : (w == 1 ? Wk : Wv);
        si = wi - (size_t)w * WQ;
        hi = g_Whi + wi * 4; lo = g_Wlo + wi * 4;
    }
    float4 v = *(const float4*)(src + si * 4);
    float a[4] = {v.x, v.y, v.z, v.w};
    uint32_t hp[2] = {0, 0}, lp[2] = {0, 0};
    #pragma unroll
    for (int i = 0; i < 4; i++) {
        __nv_bfloat16 h = __float2bfloat16(a[i]);
        __nv_bfloat16 l = __float2bfloat16(a[i] - __bfloat162float(h));
        hp[i >> 1] |= (uint32_t)__bfloat16_as_ushort(h) << ((i & 1) * 16);
        lp[i >> 1] |= (uint32_t)__bfloat16_as_ushort(l) << ((i & 1) * 16);
    }
    *(uint2*)hi = make_uint2(hp[0], hp[1]);
    *(uint2*)lo = make_uint2(lp[0], lp[1]);
}

// ---------------- Kernel 1: HMMA projection GEMM ---------------------------
// Y[m][n] = sum_k X[m][k]*W[n][k] via bf16 hi/lo split (3 mma products).
// CTA tile 128x128, K staged 64, cp.async double buffer, SW128 smem, ldmatrix.
// SMEM per stage: Ahi | Alo | Bhi | Blo, each 128 rows x 128B.
#define PROJ_SMEM_BYTES (2 * 65536)
__global__ __launch_bounds__(256) void proj_mma()
{
    extern __shared__ char smem[];
    uint32_t smem_base;
    asm("{ .reg .u64 t; cvta.to.shared.u64 t, %1; cvt.u32.u64 %0, t; }"
        : "=r"(smem_base) : "l"(smem));
    const int tid = threadIdx.x, wid = tid >> 5, lane = tid & 31;
    const int n0 = blockIdx.x * 128, m0 = blockIdx.y * 128, gz = blockIdx.z;
    const size_t a_row0 = (size_t)(gz == 0 ? 0 : MROWS) + m0;
    const __nv_bfloat16* Whi = g_Whi + (size_t)gz * DIMM * DIMM;
    const __nv_bfloat16* Wlo = g_Wlo + (size_t)gz * DIMM * DIMM;
    float* Y = (gz == 0) ? g_Q : (gz == 1 ? g_K : g_V);

    // loader mapping: 16B per thread per tile-pass
    const int lrow = tid >> 3, lseg = tid & 7;
    const uint32_t lsw = SW128((uint32_t)(lrow * 128 + lseg * 16));

    // warp tiling: 4 (m) x 2 (n); warp tile 32m x 64n
    const int m_base = (wid >> 1) * 32;
    const int n_base = (wid & 1) * 64;

    float acc[2][8][4] = {};   // [mfrag][nfrag][reg]

    auto load_stage = [&](int kc) {
        const uint32_t stg = smem_base + (uint32_t)(kc & 1) * 65536u;
        #pragma unroll
        for (int r = 0; r < 4; r++) {
            int row = lrow + r * 32;
            uint32_t sw = SW128((uint32_t)(row * 128 + lseg * 16));
            size_t ga = (a_row0 + row) * DIMM + (size_t)kc * 64 + lseg * 8;
            size_t gb = (size_t)(n0 + row) * DIMM + (size_t)kc * 64 + lseg * 8;
            cp_async16(stg + sw,          g_Xhi + ga);
            cp_async16(stg + 16384 + sw,  g_Xlo + ga);
            cp_async16(stg + 32768 + sw,  Whi + gb);
            cp_async16(stg + 49152 + sw,  Wlo + gb);
        }
        CP_COMMIT();
    };

    load_stage(0);
    for (int kc = 0; kc < 8; kc++) {
        if (kc < 7) { load_stage(kc + 1); CP_WAIT(1); }
        else        { CP_WAIT(0); }
        __syncthreads();
        const uint32_t stg = smem_base + (uint32_t)(kc & 1) * 65536u;

        #pragma unroll
        for (int t = 0; t < 4; t++) {
            const int kbyte = t * 32;
            // A fragments (hi & lo share swizzled offsets, different tile base)
            uint32_t ahi[2][4], alo[2][4];
            #pragma unroll
            for (int f = 0; f < 2; f++) {
                uint32_t boff = (uint32_t)((m_base + f * 16 + (lane & 15)) * 128
                               + kbyte + ((lane >> 4) * 16));
                uint32_t sw = SW128(boff);
                ldmx4(stg + sw, ahi[f]);
                ldmx4(stg + 16384 + sw, alo[f]);
            }
            // B fragments: 4 x ldmatrix.x4, each covers 16 n-rows (2 nfrags)
            uint32_t bhi[8][2], blo[8][2];
            #pragma unroll
            for (int p = 0; p < 4; p++) {
                int row = n_base + p * 16 + (lane & 7) + ((lane & 16) >> 1);
                uint32_t boff = (uint32_t)(row * 128 + kbyte + (lane & 8) * 2);
                uint32_t sw = SW128(boff);
                uint32_t rh[4], rl[4];
                ldmx4(stg + 32768 + sw, rh);
                ldmx4(stg + 49152 + sw, rl);
                bhi[p*2][0] = rh[0]; bhi[p*2][1] = rh[1];
                bhi[p*2+1][0] = rh[2]; bhi[p*2+1][1] = rh[3];
                blo[p*2][0] = rl[0]; blo[p*2][1] = rl[1];
                blo[p*2+1][0] = rl[2]; blo[p*2+1][1] = rl[3];
            }
            #pragma unroll
            for (int f = 0; f < 2; f++)
                #pragma unroll
                for (int nf = 0; nf < 8; nf++) {
                    mma16816(acc[f][nf], ahi[f], bhi[nf]);
                    mma16816(acc[f][nf], ahi[f], blo[nf]);
                    mma16816(acc[f][nf], alo[f], bhi[nf]);
                }
        }
        __syncthreads();
    }

    // epilogue: D frag layout -> gmem
    const int r0 = lane >> 2, c0 = (lane & 3) * 2;
    #pragma unroll
    for (int f = 0; f < 2; f++) {
        int row = m0 + m_base + f * 16 + r0;
        #pragma unroll
        for (int nf = 0; nf < 8; nf++) {
            int col = n0 + n_base + nf * 8 + c0;
            *(float2*)&Y[(size_t)row * DIMM + col] =
                make_float2(acc[f][nf][0], acc[f][nf][1]);
            *(float2*)&Y[(size_t)(row + 8) * DIMM + col] =
                make_float2(acc[f][nf][2], acc[f][nf][3]);
        }
    }
}

// ---------------- Kernel 2: softmax over groups of 32 (in-place Q, K) -----
__global__ __launch_bounds__(256) void softmax32()
{
    const int total = MROWS * HH;
    int g = blockIdx.x * 8 + (threadIdx.x >> 5);
    const int lane = threadIdx.x & 31;
    float* buf = g_Q;
    if (g >= total) { buf = g_K; g -= total; }
    if (g >= total) return;

    float x = buf[(size_t)g * 32 + lane];
    float mx = x;
    #pragma unroll
    for (int o = 16; o; o >>= 1) mx = fmaxf(mx, __shfl_xor_sync(~0u, mx, o));
    float e = __expf(x - mx);
    float s = e;
    #pragma unroll
    for (int o = 16; o; o >>= 1) s += __shfl_xor_sync(~0u, s, o);
    buf[(size_t)g * 32 + lane] = e / s;
}

// ---------------- Kernel 3: per-chunk sums  CS = K_chunk^T @ V_chunk ------
__global__ __launch_bounds__(256) void chunk_sum()
{
    __shared__ float Ks[TCH][36];
    __shared__ float Vs[TCH][36];
    const int c = blockIdx.x, h = blockIdx.y, n = blockIdx.z;
    const size_t base = ((size_t)(n * LSEQ + c * TCH)) * DIMM + h * DD;
    const int tid = threadIdx.x;

    #pragma unroll
    for (int r = 0; r < 4; r++) {
        int fidx = tid + r * 256;
        int t = fidx >> 3, dq = fidx & 7;
        *(float4*)&Ks[t][dq*4] = *(const float4*)&g_K[base + (size_t)t * DIMM + dq * 4];
        *(float4*)&Vs[t][dq*4] = *(const float4*)&g_V[base + (size_t)t * DIMM + dq * 4];
    }
    __syncthreads();

    const int d = tid >> 3, e0 = (tid & 7) * 4;
    float a0 = 0.f, a1 = 0.f, a2 = 0.f, a3 = 0.f;
    #pragma unroll 4
    for (int t = 0; t < TCH; t++) {
        float kd = Ks[t][d];
        float4 v = *(const float4*)&Vs[t][e0];
        a0 = fmaf(kd, v.x, a0); a1 = fmaf(kd, v.y, a1);
        a2 = fmaf(kd, v.z, a2); a3 = fmaf(kd, v.w, a3);
    }
    size_t outp = ((size_t)((n * HH + h) * CCH + c)) * 1024 + d * 32 + e0;
    *(float4*)&g_CS[outp] = make_float4(a0, a1, a2, a3);
}

// ---------------- Kernel 4: exclusive prefix over chunks ------------------
__global__ __launch_bounds__(1024) void prefix_state()
{
    const int bh = blockIdx.x;
    const int tid = threadIdx.x;
    float acc = 0.f;
    size_t base = (size_t)bh * CCH * 1024 + tid;
    #pragma unroll
    for (int c = 0; c < CCH; c++) {
        g_S0[base + (size_t)c * 1024] = acc;
        acc += g_CS[base + (size_t)c * 1024];
    }
}

// ---------------- Kernel 5: intra-chunk causal attention ------------------
#define ATTN_SMEM_FLOATS (36*128*3 + 36*32 + 132*128)
__global__ __launch_bounds__(256) void chunk_attn(float* __restrict__ out)
{
    extern __shared__ float sm[];
    float (*Qs)[36]  = (float(*)[36])(sm);
    float (*Ks)[36]  = (float(*)[36])(sm + 4608);
    float (*Vs)[36]  = (float(*)[36])(sm + 9216);
    float (*S0)[36]  = (float(*)[36])(sm + 13824);
    float (*As)[132] = (float(*)[132])(sm + 14976);

    const int c = blockIdx.x, h = blockIdx.y, n = blockIdx.z;
    const int tid = threadIdx.x;
    const int tx = tid & 15, ty = tid >> 4;
    const size_t base = ((size_t)(n * LSEQ + c * TCH)) * DIMM + h * DD;

    #pragma unroll
    for (int r = 0; r < 4; r++) {
        int fidx = tid + r * 256;
        int t = fidx >> 3, dq = fidx & 7;
        size_t g = base + (size_t)t * DIMM + dq * 4;
        *(float4*)&Qs[t][dq*4] = *(const float4*)&g_Q[g];
        *(float4*)&Ks[t][dq*4] = *(const float4*)&g_K[g];
        *(float4*)&Vs[t][dq*4] = *(const float4*)&g_V[g];
    }
    {
        size_t sbase = ((size_t)((n * HH + h) * CCH + c)) * 1024;
        float4 s = *(const float4*)&g_S0[sbase + (size_t)tid * 4];
        int d = (tid * 4) >> 5, e = (tid * 4) & 31;
        *(float4*)&S0[d][e] = s;
    }
    __syncthreads();

    float acc[8][8] = {};
    #pragma unroll
    for (int dq = 0; dq < 8; dq++) {
        float4 kq[8];
        #pragma unroll
        for (int jj = 0; jj < 8; jj++)
            kq[jj] = *(const float4*)&Ks[tx + jj * 16][dq * 4];
        #pragma unroll
        for (int ii = 0; ii < 8; ii++) {
            float4 q = *(const float4*)&Qs[ty + ii * 16][dq * 4];
            #pragma unroll
            for (int jj = 0; jj < 8; jj++) {
                acc[ii][jj] = fmaf(q.x, kq[jj].x, acc[ii][jj]);
                acc[ii][jj] = fmaf(q.y, kq[jj].y, acc[ii][jj]);
                acc[ii][jj] = fmaf(q.z, kq[jj].z, acc[ii][jj]);
                acc[ii][jj] = fmaf(q.w, kq[jj].w, acc[ii][jj]);
            }
        }
    }
    #pragma unroll
    for (int ii = 0; ii < 8; ii++) {
        int i = ty + ii * 16;
        #pragma unroll
        for (int jj = 0; jj < 8; jj++) {
            int j = tx + jj * 16;
            As[i][j] = (j <= i) ? acc[ii][jj] : 0.0f;
        }
    }
    __syncthreads();

    float o0[8] = {}, o1[8] = {};
    #pragma unroll 4
    for (int d = 0; d < 32; d++) {
        float s0 = S0[d][tx * 2], s1 = S0[d][tx * 2 + 1];
        #pragma unroll
        for (int ii = 0; ii < 8; ii++) {
            float q = Qs[ty + ii * 16][d];
            o0[ii] = fmaf(q, s0, o0[ii]);
            o1[ii] = fmaf(q, s1, o1[ii]);
        }
    }
    #pragma unroll 4
    for (int j = 0; j < TCH; j++) {
        float v0 = Vs[j][tx * 2], v1 = Vs[j][tx * 2 + 1];
        #pragma unroll
        for (int ii = 0; ii < 8; ii++) {
            float a = As[ty + ii * 16][j];
            o0[ii] = fmaf(a, v0, o0[ii]);
            o1[ii] = fmaf(a, v1, o1[ii]);
        }
    }
    #pragma unroll
    for (int ii = 0; ii < 8; ii++) {
        int i = ty + ii * 16;
        *(float2*)&out[base + (size_t)i * DIMM + tx * 2] = make_float2(o0[ii], o1[ii]);
    }
}

// ---------------- launch ---------------------------------------------------
extern "C" void kernel_launch(void* const* d_in, const int* in_sizes, int n_in,
                              void* d_out, int out_size)
{
    const float* query = (const float*)d_in[0];
    const float* key   = (const float*)d_in[1];
    const float* Wq    = (const float*)d_in[2];
    const float* Wk    = (const float*)d_in[3];
    const float* Wv    = (const float*)d_in[4];
    float* out = (float*)d_out;

    cudaFuncSetAttribute(proj_mma, cudaFuncAttributeMaxDynamicSharedMemorySize,
                         PROJ_SMEM_BYTES);
    cudaFuncSetAttribute(chunk_attn, cudaFuncAttributeMaxDynamicSharedMemorySize,
                         ATTN_SMEM_FLOATS * (int)sizeof(float));

    // 0) split fp32 -> bf16 hi/lo (X and W)
    {
        const size_t XQ = (size_t)2 * MROWS * DIMM / 4;
        const size_t WQ = (size_t)DIMM * DIMM / 4;
        int blocks = (int)((XQ + 3 * WQ + 255) / 256);
        split_bf16<<<blocks, 256>>>(query, key, Wq, Wk, Wv);
    }
    // 1) three projections on HMMA tensor path
    proj_mma<<<dim3(DIMM / 128, MROWS / 128, 3), 256, PROJ_SMEM_BYTES>>>();
    // 2) softmax over D=32 for Q and K (in place)
    softmax32<<<(2 * MROWS * HH) / 8, 256>>>();
    // 3) per-chunk K^T V sums
    chunk_sum<<<dim3(CCH, HH, NB), 256>>>();
    // 4) exclusive prefix of chunk states
    prefix_state<<<NB * HH, 1024>>>();
    // 5) intra-chunk causal attention + output
    chunk_attn<<<dim3(CCH, HH, NB), 256, ATTN_SMEM_FLOATS * (int)sizeof(float)>>>(out);
}

// round 5
// speedup vs baseline: 3.1088x; 1.2754x over previous
#include <cuda_runtime.h>
#include <cuda_bf16.h>
#include <cstdint>

// Problem constants
#define NB    4
#define LSEQ  2048
#define HH    16
#define DD    32
#define DIMM  512
#define MROWS (NB*LSEQ)      // 8192
#define TCH   128            // chunk length
#define CCH   (LSEQ/TCH)     // 16 chunks

// ---------------- scratch (device globals; no allocations) ----------------
__device__ __nv_bfloat16 g_Qhi[(size_t)MROWS*DIMM];
__device__ __nv_bfloat16 g_Qlo[(size_t)MROWS*DIMM];
__device__ __nv_bfloat16 g_Khi[(size_t)MROWS*DIMM];
__device__ __nv_bfloat16 g_Klo[(size_t)MROWS*DIMM];
__device__ __nv_bfloat16 g_Vhi[(size_t)MROWS*DIMM];
__device__ __nv_bfloat16 g_Vlo[(size_t)MROWS*DIMM];
__device__ float g_CS[(size_t)NB*HH*CCH*DD*DD];
__device__ float g_S0[(size_t)NB*HH*CCH*DD*DD];
__device__ __nv_bfloat16 g_Xhi[(size_t)2*MROWS*DIMM];  // query rows then key rows
__device__ __nv_bfloat16 g_Xlo[(size_t)2*MROWS*DIMM];
__device__ __nv_bfloat16 g_Whi[(size_t)3*DIMM*DIMM];   // Wq, Wk, Wv
__device__ __nv_bfloat16 g_Wlo[(size_t)3*DIMM*DIMM];

// ---------------- PTX helpers ----------------------------------------------
__device__ __forceinline__ void ldmx4(uint32_t addr, uint32_t* r) {
    asm volatile("ldmatrix.sync.aligned.m8n8.x4.shared.b16 {%0,%1,%2,%3}, [%4];"
        : "=r"(r[0]), "=r"(r[1]), "=r"(r[2]), "=r"(r[3]) : "r"(addr));
}
__device__ __forceinline__ void ldmx4t(uint32_t addr, uint32_t* r) {
    asm volatile("ldmatrix.sync.aligned.m8n8.x4.trans.shared.b16 {%0,%1,%2,%3}, [%4];"
        : "=r"(r[0]), "=r"(r[1]), "=r"(r[2]), "=r"(r[3]) : "r"(addr));
}
__device__ __forceinline__ void mma16816(float* d, const uint32_t* a, const uint32_t* b) {
    asm volatile("mma.sync.aligned.m16n8k16.row.col.f32.bf16.bf16.f32 "
        "{%0,%1,%2,%3}, {%4,%5,%6,%7}, {%8,%9}, {%0,%1,%2,%3};"
        : "+f"(d[0]), "+f"(d[1]), "+f"(d[2]), "+f"(d[3])
        : "r"(a[0]), "r"(a[1]), "r"(a[2]), "r"(a[3]), "r"(b[0]), "r"(b[1]));
}
__device__ __forceinline__ void cp_async16(uint32_t dst, const void* src) {
    asm volatile("cp.async.cg.shared.global [%0], [%1], 16;" :: "r"(dst), "l"(src) : "memory");
}
#define CP_COMMIT()  asm volatile("cp.async.commit_group;" ::: "memory")
#define CP_WAIT(n)   asm volatile("cp.async.wait_group %0;" :: "n"(n) : "memory")
#define SW128(off)   ((off) ^ (((off) >> 3) & 0x70u))

__device__ __forceinline__ uint32_t smem_u32(const void* p) {
    uint32_t a;
    asm("{ .reg .u64 t; cvta.to.shared.u64 t, %1; cvt.u32.u64 %0, t; }" : "=r"(a) : "l"(p));
    return a;
}
__device__ __forceinline__ uint32_t packbf(float x, float y) {
    __nv_bfloat162 t = __floats2bfloat162_rn(x, y);
    return *(uint32_t*)&t;
}
// hi/lo split of a float pair into two packed bf16x2
__device__ __forceinline__ void split2(float x, float y, uint32_t& hi, uint32_t& lo) {
    __nv_bfloat16 hx = __float2bfloat16(x), hy = __float2bfloat16(y);
    float rx = x - __bfloat162float(hx), ry = y - __bfloat162float(hy);
    __nv_bfloat162 h; h.x = hx; h.y = hy;
    __nv_bfloat162 l = __floats2bfloat162_rn(rx, ry);
    hi = *(uint32_t*)&h; lo = *(uint32_t*)&l;
}

// ---------------- Kernel 0: fp32 -> bf16 hi/lo split (inputs) --------------
__global__ __launch_bounds__(256) void split_bf16(
    const float* __restrict__ query, const float* __restrict__ key,
    const float* __restrict__ Wq, const float* __restrict__ Wk,
    const float* __restrict__ Wv)
{
    const size_t XQ = (size_t)2 * MROWS * DIMM / 4;
    const size_t WQ = (size_t)DIMM * DIMM / 4;
    size_t qi = (size_t)blockIdx.x * 256 + threadIdx.x;
    const float* src; __nv_bfloat16 *hi, *lo; size_t si;
    if (qi < XQ) {
        size_t half = XQ / 2;
        src = (qi < half) ? query : key;
        si = (qi < half) ? qi : qi - half;
        hi = g_Xhi + qi * 4; lo = g_Xlo + qi * 4;
    } else {
        size_t wi = qi - XQ;
        if (wi >= 3 * WQ) return;
        int w = (int)(wi / WQ);
        src = (w == 0) ? Wq : (w == 1 ? Wk : Wv);
        si = wi - (size_t)w * WQ;
        hi = g_Whi + wi * 4; lo = g_Wlo + wi * 4;
    }
    float4 v = *(const float4*)(src + si * 4);
    uint32_t h0, l0, h1, l1;
    split2(v.x, v.y, h0, l0);
    split2(v.z, v.w, h1, l1);
    *(uint2*)hi = make_uint2(h0, h1);
    *(uint2*)lo = make_uint2(l0, l1);
}

// ---------------- Kernel 1: HMMA projection + fused softmax + split --------
#define PROJ_SMEM_BYTES (2 * 65536)
__global__ __launch_bounds__(256) void proj_mma()
{
    extern __shared__ char smem[];
    uint32_t smem_base = smem_u32(smem);
    const int tid = threadIdx.x, wid = tid >> 5, lane = tid & 31;
    const int n0 = blockIdx.x * 128, m0 = blockIdx.y * 128, gz = blockIdx.z;
    const size_t a_row0 = (size_t)(gz == 0 ? 0 : MROWS) + m0;
    const __nv_bfloat16* Whi = g_Whi + (size_t)gz * DIMM * DIMM;
    const __nv_bfloat16* Wlo = g_Wlo + (size_t)gz * DIMM * DIMM;
    __nv_bfloat16* Yhi = (gz == 0) ? g_Qhi : (gz == 1 ? g_Khi : g_Vhi);
    __nv_bfloat16* Ylo = (gz == 0) ? g_Qlo : (gz == 1 ? g_Klo : g_Vlo);

    const int lrow = tid >> 3, lseg = tid & 7;
    const int m_base = (wid >> 1) * 32;
    const int n_base = (wid & 1) * 64;

    float acc[2][8][4] = {};

    auto load_stage = [&](int kc) {
        const uint32_t stg = smem_base + (uint32_t)(kc & 1) * 65536u;
        #pragma unroll
        for (int r = 0; r < 4; r++) {
            int row = lrow + r * 32;
            uint32_t sw = SW128((uint32_t)(row * 128 + lseg * 16));
            size_t ga = (a_row0 + row) * DIMM + (size_t)kc * 64 + lseg * 8;
            size_t gb = (size_t)(n0 + row) * DIMM + (size_t)kc * 64 + lseg * 8;
            cp_async16(stg + sw,          g_Xhi + ga);
            cp_async16(stg + 16384 + sw,  g_Xlo + ga);
            cp_async16(stg + 32768 + sw,  Whi + gb);
            cp_async16(stg + 49152 + sw,  Wlo + gb);
        }
        CP_COMMIT();
    };

    load_stage(0);
    for (int kc = 0; kc < 8; kc++) {
        if (kc < 7) { load_stage(kc + 1); CP_WAIT(1); }
        else        { CP_WAIT(0); }
        __syncthreads();
        const uint32_t stg = smem_base + (uint32_t)(kc & 1) * 65536u;

        #pragma unroll
        for (int t = 0; t < 4; t++) {
            const int kbyte = t * 32;
            uint32_t ahi[2][4], alo[2][4];
            #pragma unroll
            for (int f = 0; f < 2; f++) {
                uint32_t boff = (uint32_t)((m_base + f * 16 + (lane & 15)) * 128
                               + kbyte + ((lane >> 4) * 16));
                uint32_t sw = SW128(boff);
                ldmx4(stg + sw, ahi[f]);
                ldmx4(stg + 16384 + sw, alo[f]);
            }
            uint32_t bhi[8][2], blo[8][2];
            #pragma unroll
            for (int p = 0; p < 4; p++) {
                int row = n_base + p * 16 + (lane & 7) + ((lane & 16) >> 1);
                uint32_t boff = (uint32_t)(row * 128 + kbyte + (lane & 8) * 2);
                uint32_t sw = SW128(boff);
                uint32_t rh[4], rl[4];
                ldmx4(stg + 32768 + sw, rh);
                ldmx4(stg + 49152 + sw, rl);
                bhi[p*2][0] = rh[0]; bhi[p*2][1] = rh[1];
                bhi[p*2+1][0] = rh[2]; bhi[p*2+1][1] = rh[3];
                blo[p*2][0] = rl[0]; blo[p*2][1] = rl[1];
                blo[p*2+1][0] = rl[2]; blo[p*2+1][1] = rl[3];
            }
            #pragma unroll
            for (int f = 0; f < 2; f++)
                #pragma unroll
                for (int nf = 0; nf < 8; nf++) {
                    mma16816(acc[f][nf], ahi[f], bhi[nf]);
                    mma16816(acc[f][nf], ahi[f], blo[nf]);
                    mma16816(acc[f][nf], alo[f], bhi[nf]);
                }
        }
        __syncthreads();
    }

    // fused softmax over 32-col head groups (cols n_base+[0,32) and +[32,64))
    if (gz < 2) {
        #pragma unroll
        for (int f = 0; f < 2; f++) {
            #pragma unroll
            for (int g = 0; g < 2; g++) {
                float mx0 = -1e30f, mx1 = -1e30f;
                #pragma unroll
                for (int nf = g*4; nf < g*4+4; nf++) {
                    mx0 = fmaxf(mx0, fmaxf(acc[f][nf][0], acc[f][nf][1]));
                    mx1 = fmaxf(mx1, fmaxf(acc[f][nf][2], acc[f][nf][3]));
                }
                mx0 = fmaxf(mx0, __shfl_xor_sync(~0u, mx0, 1));
                mx0 = fmaxf(mx0, __shfl_xor_sync(~0u, mx0, 2));
                mx1 = fmaxf(mx1, __shfl_xor_sync(~0u, mx1, 1));
                mx1 = fmaxf(mx1, __shfl_xor_sync(~0u, mx1, 2));
                float s0 = 0.f, s1 = 0.f;
                #pragma unroll
                for (int nf = g*4; nf < g*4+4; nf++) {
                    acc[f][nf][0] = __expf(acc[f][nf][0] - mx0);
                    acc[f][nf][1] = __expf(acc[f][nf][1] - mx0);
                    acc[f][nf][2] = __expf(acc[f][nf][2] - mx1);
                    acc[f][nf][3] = __expf(acc[f][nf][3] - mx1);
                    s0 += acc[f][nf][0] + acc[f][nf][1];
                    s1 += acc[f][nf][2] + acc[f][nf][3];
                }
                s0 += __shfl_xor_sync(~0u, s0, 1);
                s0 += __shfl_xor_sync(~0u, s0, 2);
                s1 += __shfl_xor_sync(~0u, s1, 1);
                s1 += __shfl_xor_sync(~0u, s1, 2);
                float r0 = 1.f / s0, r1 = 1.f / s1;
                #pragma unroll
                for (int nf = g*4; nf < g*4+4; nf++) {
                    acc[f][nf][0] *= r0; acc[f][nf][1] *= r0;
                    acc[f][nf][2] *= r1; acc[f][nf][3] *= r1;
                }
            }
        }
    }

    // split to bf16 hi/lo and store
    const int r0 = lane >> 2, c0 = (lane & 3) * 2;
    #pragma unroll
    for (int f = 0; f < 2; f++) {
        int row = m0 + m_base + f * 16 + r0;
        #pragma unroll
        for (int nf = 0; nf < 8; nf++) {
            int col = n0 + n_base + nf * 8 + c0;
            uint32_t h, l;
            split2(acc[f][nf][0], acc[f][nf][1], h, l);
            *(uint32_t*)&Yhi[(size_t)row * DIMM + col] = h;
            *(uint32_t*)&Ylo[(size_t)row * DIMM + col] = l;
            split2(acc[f][nf][2], acc[f][nf][3], h, l);
            *(uint32_t*)&Yhi[(size_t)(row + 8) * DIMM + col] = h;
            *(uint32_t*)&Ylo[(size_t)(row + 8) * DIMM + col] = l;
        }
    }
}

// ---------------- Kernel 3: HMMA chunk sums CS = K^T V ---------------------
// Per block (64 thr): 32x32 = K[128,32]^T @ V[128,32]. Trans ldmatrix both.
#define TS 80   // smem row stride bytes (64B data + 16 pad)
__global__ __launch_bounds__(64) void chunk_sum()
{
    __shared__ char sm[4 * 128 * TS];
    uint32_t sb = smem_u32(sm);
    const uint32_t Khi_s = sb, Klo_s = sb + 128*TS, Vhi_s = sb + 2*128*TS, Vlo_s = sb + 3*128*TS;
    const int c = blockIdx.x, h = blockIdx.y, n = blockIdx.z;
    const int tid = threadIdx.x, w = tid >> 5, lane = tid & 31;
    const size_t base = ((size_t)(n * LSEQ + c * TCH)) * DIMM + h * DD;

    #pragma unroll
    for (int r = 0; r < 8; r++) {
        int idx = tid + r * 64;       // 0..511
        int row = idx >> 2, seg = idx & 3;
        size_t g = base + (size_t)row * DIMM + seg * 8;
        uint32_t so = (uint32_t)(row * TS + seg * 16);
        *(uint4*)(sm + 0*128*TS + so) = *(const uint4*)(g_Khi + g);
        *(uint4*)(sm + 1*128*TS + so) = *(const uint4*)(g_Klo + g);
        *(uint4*)(sm + 2*128*TS + so) = *(const uint4*)(g_Vhi + g);
        *(uint4*)(sm + 3*128*TS + so) = *(const uint4*)(g_Vlo + g);
    }
    __syncthreads();

    const int m0 = w * 16;   // d rows for this warp
    float acc[4][4] = {};
    // A (K^T) trans addressing: row = k0+(lane&7)+((lane>>4)<<3), col = m0+((lane>>3)&1)*8
    const uint32_t a_off = (uint32_t)(((lane & 7) + ((lane >> 4) << 3)) * TS
                         + (m0 + ((lane >> 3) & 1) * 8) * 2);
    // B (V) trans addressing: row = k0+(lane&15), col = e0+(lane>>4)*8
    const uint32_t b_off = (uint32_t)((lane & 15) * TS + ((lane >> 4) * 8) * 2);

    #pragma unroll
    for (int kk = 0; kk < 8; kk++) {
        const uint32_t krow = (uint32_t)(kk * 16) * TS;
        uint32_t ahi[4], alo[4];
        ldmx4t(Khi_s + krow + a_off, ahi);
        ldmx4t(Klo_s + krow + a_off, alo);
        #pragma unroll
        for (int q = 0; q < 2; q++) {
            uint32_t bh[4], bl[4];
            ldmx4t(Vhi_s + krow + b_off + q * 32, bh);
            ldmx4t(Vlo_s + krow + b_off + q * 32, bl);
            #pragma unroll
            for (int s = 0; s < 2; s++) {
                int nf = q * 2 + s;
                mma16816(acc[nf], ahi, bh + s * 2);
                mma16816(acc[nf], ahi, bl + s * 2);
                mma16816(acc[nf], alo, bh + s * 2);
            }
        }
    }
    size_t ob = ((size_t)((n * HH + h) * CCH + c)) * 1024;
    const int dr = m0 + (lane >> 2), ec = (lane & 3) * 2;
    #pragma unroll
    for (int nf = 0; nf < 4; nf++) {
        *(float2*)&g_CS[ob + (size_t)dr * 32 + nf * 8 + ec] = make_float2(acc[nf][0], acc[nf][1]);
        *(float2*)&g_CS[ob + (size_t)(dr + 8) * 32 + nf * 8 + ec] = make_float2(acc[nf][2], acc[nf][3]);
    }
}

// ---------------- Kernel 4: exclusive prefix over chunks ------------------
__global__ __launch_bounds__(1024) void prefix_state()
{
    const int bh = blockIdx.x;
    const int tid = threadIdx.x;
    float acc = 0.f;
    size_t base = (size_t)bh * CCH * 1024 + tid;
    #pragma unroll
    for (int c = 0; c < CCH; c++) {
        g_S0[base + (size_t)c * 1024] = acc;
        acc += g_CS[base + (size_t)c * 1024];
    }
}

// ---------------- Kernel 5: HMMA intra-chunk causal attention --------------
// Phase A: A = Q K^T (k=32), warp tile 16m x 128n -> A stays in registers.
// Phase B: out = A @ V (k=128, V via trans ldmatrix) + Q @ S0 (k=32).
#define ATTN_SMEM_BYTES (6*128*TS + 2*32*TS)
__global__ __launch_bounds__(256) void chunk_attn(float* __restrict__ out)
{
    extern __shared__ char sm[];
    uint32_t sb = smem_u32(sm);
    const uint32_t Qhi_s = sb,            Qlo_s = sb + 128*TS;
    const uint32_t Khi_s = sb + 2*128*TS, Klo_s = sb + 3*128*TS;
    const uint32_t Vhi_s = sb + 4*128*TS, Vlo_s = sb + 5*128*TS;
    const uint32_t Shi_s = sb + 6*128*TS, Slo_s = sb + 6*128*TS + 32*TS;

    const int c = blockIdx.x, h = blockIdx.y, n = blockIdx.z;
    const int tid = threadIdx.x, wid = tid >> 5, lane = tid & 31;
    const size_t base = ((size_t)(n * LSEQ + c * TCH)) * DIMM + h * DD;

    // load Q,K,V hi/lo tiles (128 x 32 bf16 each)
    #pragma unroll
    for (int r = 0; r < 2; r++) {
        int idx = tid + r * 256;      // 0..511
        int row = idx >> 2, seg = idx & 3;
        size_t g = base + (size_t)row * DIMM + seg * 8;
        uint32_t so = (uint32_t)(row * TS + seg * 16);
        *(uint4*)(sm + 0*128*TS + so) = *(const uint4*)(g_Qhi + g);
        *(uint4*)(sm + 1*128*TS + so) = *(const uint4*)(g_Qlo + g);
        *(uint4*)(sm + 2*128*TS + so) = *(const uint4*)(g_Khi + g);
        *(uint4*)(sm + 3*128*TS + so) = *(const uint4*)(g_Klo + g);
        *(uint4*)(sm + 4*128*TS + so) = *(const uint4*)(g_Vhi + g);
        *(uint4*)(sm + 5*128*TS + so) = *(const uint4*)(g_Vlo + g);
    }
    {   // S0 (32x32 fp32) -> bf16 hi/lo in smem
        size_t sbase = ((size_t)((n * HH + h) * CCH + c)) * 1024;
        int d = tid >> 3, e0 = (tid & 7) * 4;
        float4 v = *(const float4*)&g_S0[sbase + (size_t)d * 32 + e0];
        uint32_t h0, l0, h1, l1;
        split2(v.x, v.y, h0, l0);
        split2(v.z, v.w, h1, l1);
        uint32_t so = (uint32_t)(d * TS + e0 * 2);
        *(uint2*)(sm + 6*128*TS + so)         = make_uint2(h0, h1);
        *(uint2*)(sm + 6*128*TS + 32*TS + so) = make_uint2(l0, l1);
    }
    __syncthreads();

    const int m_base = wid * 16;

    // --- Phase A: A[i][j] for i in warp's 16 rows, j in 0..127 -------------
    // Q a-frags (reused in Phase B for Q@S0)
    uint32_t qhi[2][4], qlo[2][4];
    {
        uint32_t a_off = (uint32_t)((m_base + (lane & 15)) * TS + (lane >> 4) * 16);
        #pragma unroll
        for (int kk = 0; kk < 2; kk++) {
            ldmx4(Qhi_s + a_off + kk * 32, qhi[kk]);
            ldmx4(Qlo_s + a_off + kk * 32, qlo[kk]);
        }
    }
    float A[16][4] = {};   // nf = j/8
    {
        // K b-frags: non-trans from [j][d] memory
        const uint32_t b_base = (uint32_t)(((lane & 7) + ((lane & 16) >> 1)) * TS + (lane & 8) * 2);
        #pragma unroll
        for (int kk = 0; kk < 2; kk++) {
            #pragma unroll
            for (int p = 0; p < 8; p++) {
                uint32_t off = b_base + (uint32_t)(p * 16) * TS + kk * 32;
                uint32_t bh[4], bl[4];
                ldmx4(Khi_s + off, bh);
                ldmx4(Klo_s + off, bl);
                #pragma unroll
                for (int s = 0; s < 2; s++) {
                    int nf = p * 2 + s;
                    mma16816(A[nf], qhi[kk], bh + s * 2);
                    mma16816(A[nf], qhi[kk], bl + s * 2);
                    mma16816(A[nf], qlo[kk], bh + s * 2);
                }
            }
        }
    }
    // causal mask: zero where j > i
    {
        const int i0 = m_base + (lane >> 2), i1 = i0 + 8;
        const int jb = (lane & 3) * 2;
        #pragma unroll
        for (int nf = 0; nf < 16; nf++) {
            int j0 = nf * 8 + jb;
            if (j0     > i0) A[nf][0] = 0.f;
            if (j0 + 1 > i0) A[nf][1] = 0.f;
            if (j0     > i1) A[nf][2] = 0.f;
            if (j0 + 1 > i1) A[nf][3] = 0.f;
        }
    }

    // --- Phase B: out = A @ V + Q @ S0 -------------------------------------
    float o[4][4] = {};
    const uint32_t bt_off = (uint32_t)((lane & 15) * TS + ((lane >> 4) * 8) * 2);
    #pragma unroll
    for (int kk = 0; kk < 8; kk++) {
        // A fragments from registers (hi/lo split on the fly)
        uint32_t ahi[4], alo[4];
        split2(A[2*kk][0],   A[2*kk][1],   ahi[0], alo[0]);
        split2(A[2*kk][2],   A[2*kk][3],   ahi[1], alo[1]);
        split2(A[2*kk+1][0], A[2*kk+1][1], ahi[2], alo[2]);
        split2(A[2*kk+1][2], A[2*kk+1][3], ahi[3], alo[3]);
        const uint32_t krow = (uint32_t)(kk * 16) * TS;
        #pragma unroll
        for (int q = 0; q < 2; q++) {
            uint32_t bh[4], bl[4];
            ldmx4t(Vhi_s + krow + bt_off + q * 32, bh);
            ldmx4t(Vlo_s + krow + bt_off + q * 32, bl);
            #pragma unroll
            for (int s = 0; s < 2; s++) {
                int nf = q * 2 + s;
                mma16816(o[nf], ahi, bh + s * 2);
                mma16816(o[nf], ahi, bl + s * 2);
                mma16816(o[nf], alo, bh + s * 2);
            }
        }
    }
    #pragma unroll
    for (int kk = 0; kk < 2; kk++) {
        const uint32_t krow = (uint32_t)(kk * 16) * TS;
        #pragma unroll
        for (int q = 0; q < 2; q++) {
            uint32_t bh[4], bl[4];
            ldmx4t(Shi_s + krow + bt_off + q * 32, bh);
            ldmx4t(Slo_s + krow + bt_off + q * 32, bl);
            #pragma unroll
            for (int s = 0; s < 2; s++) {
                int nf = q * 2 + s;
                mma16816(o[nf], qhi[kk], bh + s * 2);
                mma16816(o[nf], qhi[kk], bl + s * 2);
                mma16816(o[nf], qlo[kk], bh + s * 2);
            }
        }
    }

    // store
    const int r0 = lane >> 2, ec = (lane & 3) * 2;
    #pragma unroll
    for (int nf = 0; nf < 4; nf++) {
        size_t p0 = base + (size_t)(m_base + r0) * DIMM + nf * 8 + ec;
        *(float2*)&out[p0]              = make_float2(o[nf][0], o[nf][1]);
        *(float2*)&out[p0 + 8 * DIMM]   = make_float2(o[nf][2], o[nf][3]);
    }
}

// ---------------- launch ---------------------------------------------------
extern "C" void kernel_launch(void* const* d_in, const int* in_sizes, int n_in,
                              void* d_out, int out_size)
{
    const float* query = (const float*)d_in[0];
    const float* key   = (const float*)d_in[1];
    const float* Wq    = (const float*)d_in[2];
    const float* Wk    = (const float*)d_in[3];
    const float* Wv    = (const float*)d_in[4];
    float* out = (float*)d_out;

    cudaFuncSetAttribute(proj_mma, cudaFuncAttributeMaxDynamicSharedMemorySize,
                         PROJ_SMEM_BYTES);
    cudaFuncSetAttribute(chunk_attn, cudaFuncAttributeMaxDynamicSharedMemorySize,
                         ATTN_SMEM_BYTES);

    // 0) split fp32 -> bf16 hi/lo (X and W)
    {
        const size_t XQ = (size_t)2 * MROWS * DIMM / 4;
        const size_t WQ = (size_t)DIMM * DIMM / 4;
        int blocks = (int)((XQ + 3 * WQ + 255) / 256);
        split_bf16<<<blocks, 256>>>(query, key, Wq, Wk, Wv);
    }
    // 1) projections + fused softmax + bf16 hi/lo output
    proj_mma<<<dim3(DIMM / 128, MROWS / 128, 3), 256, PROJ_SMEM_BYTES>>>();
    // 2) per-chunk K^T V sums (HMMA)
    chunk_sum<<<dim3(CCH, HH, NB), 64>>>();
    // 3) exclusive prefix of chunk states
    prefix_state<<<NB * HH, 1024>>>();
    // 4) intra-chunk causal attention + output (HMMA)
    chunk_attn<<<dim3(CCH, HH, NB), 256, ATTN_SMEM_BYTES>>>(out);
}

// round 6
// speedup vs baseline: 3.4323x; 1.1040x over previous
#include <cuda_runtime.h>
#include <cuda_bf16.h>
#include <cstdint>

// Problem constants
#define NB    4
#define LSEQ  2048
#define HH    16
#define DD    32
#define DIMM  512
#define MROWS (NB*LSEQ)      // 8192
#define TCH   128            // chunk length
#define CCH   (LSEQ/TCH)     // 16 chunks

// ---------------- scratch (device globals; no allocations) ----------------
__device__ __nv_bfloat16 g_Qhi[(size_t)MROWS*DIMM];
__device__ __nv_bfloat16 g_Qlo[(size_t)MROWS*DIMM];
__device__ __nv_bfloat16 g_Khi[(size_t)MROWS*DIMM];
__device__ __nv_bfloat16 g_Klo[(size_t)MROWS*DIMM];
__device__ __nv_bfloat16 g_Vhi[(size_t)MROWS*DIMM];
__device__ __nv_bfloat16 g_Vlo[(size_t)MROWS*DIMM];
__device__ float g_CS[(size_t)NB*HH*CCH*DD*DD];
__device__ float g_S0[(size_t)NB*HH*CCH*DD*DD];
__device__ __nv_bfloat16 g_Xhi[(size_t)2*MROWS*DIMM];  // query rows then key rows
__device__ __nv_bfloat16 g_Xlo[(size_t)2*MROWS*DIMM];
__device__ __nv_bfloat16 g_Whi[(size_t)3*DIMM*DIMM];   // Wq, Wk, Wv
__device__ __nv_bfloat16 g_Wlo[(size_t)3*DIMM*DIMM];

// ---------------- PTX helpers ----------------------------------------------
__device__ __forceinline__ void ldmx4(uint32_t addr, uint32_t* r) {
    asm volatile("ldmatrix.sync.aligned.m8n8.x4.shared.b16 {%0,%1,%2,%3}, [%4];"
        : "=r"(r[0]), "=r"(r[1]), "=r"(r[2]), "=r"(r[3]) : "r"(addr));
}
__device__ __forceinline__ void ldmx4t(uint32_t addr, uint32_t* r) {
    asm volatile("ldmatrix.sync.aligned.m8n8.x4.trans.shared.b16 {%0,%1,%2,%3}, [%4];"
        : "=r"(r[0]), "=r"(r[1]), "=r"(r[2]), "=r"(r[3]) : "r"(addr));
}
__device__ __forceinline__ void mma16816(float* d, const uint32_t* a, const uint32_t* b) {
    asm volatile("mma.sync.aligned.m16n8k16.row.col.f32.bf16.bf16.f32 "
        "{%0,%1,%2,%3}, {%4,%5,%6,%7}, {%8,%9}, {%0,%1,%2,%3};"
        : "+f"(d[0]), "+f"(d[1]), "+f"(d[2]), "+f"(d[3])
        : "r"(a[0]), "r"(a[1]), "r"(a[2]), "r"(a[3]), "r"(b[0]), "r"(b[1]));
}
__device__ __forceinline__ void cp_async16(uint32_t dst, const void* src) {
    asm volatile("cp.async.cg.shared.global [%0], [%1], 16;" :: "r"(dst), "l"(src) : "memory");
}
#define CP_COMMIT()  asm volatile("cp.async.commit_group;" ::: "memory")
#define CP_WAIT(n)   asm volatile("cp.async.wait_group %0;" :: "n"(n) : "memory")
#define SW128(off)   ((off) ^ (((off) >> 3) & 0x70u))

__device__ __forceinline__ uint32_t smem_u32(const void* p) {
    uint32_t a;
    asm("{ .reg .u64 t; cvta.to.shared.u64 t, %1; cvt.u32.u64 %0, t; }" : "=r"(a) : "l"(p));
    return a;
}
// hi/lo split of a float pair into two packed bf16x2
__device__ __forceinline__ void split2(float x, float y, uint32_t& hi, uint32_t& lo) {
    __nv_bfloat16 hx = __float2bfloat16(x), hy = __float2bfloat16(y);
    float rx = x - __bfloat162float(hx), ry = y - __bfloat162float(hy);
    __nv_bfloat162 h; h.x = hx; h.y = hy;
    __nv_bfloat162 l = __floats2bfloat162_rn(rx, ry);
    hi = *(uint32_t*)&h; lo = *(uint32_t*)&l;
}

// ---------------- Kernel 0: fp32 -> bf16 hi/lo split (inputs) --------------
__global__ __launch_bounds__(256) void split_bf16(
    const float* __restrict__ query, const float* __restrict__ key,
    const float* __restrict__ Wq, const float* __restrict__ Wk,
    const float* __restrict__ Wv)
{
    const size_t XQ = (size_t)2 * MROWS * DIMM / 4;
    const size_t WQ = (size_t)DIMM * DIMM / 4;
    size_t qi = (size_t)blockIdx.x * 256 + threadIdx.x;
    const float* src; __nv_bfloat16 *hi, *lo; size_t si;
    if (qi < XQ) {
        size_t half = XQ / 2;
        src = (qi < half) ? query : key;
        si = (qi < half) ? qi : qi - half;
        hi = g_Xhi + qi * 4; lo = g_Xlo + qi * 4;
    } else {
        size_t wi = qi - XQ;
        if (wi >= 3 * WQ) return;
        int w = (int)(wi / WQ);
        src = (w == 0) ? Wq : (w == 1 ? Wk : Wv);
        si = wi - (size_t)w * WQ;
        hi = g_Whi + wi * 4; lo = g_Wlo + wi * 4;
    }
    float4 v = *(const float4*)(src + si * 4);
    uint32_t h0, l0, h1, l1;
    split2(v.x, v.y, h0, l0);
    split2(v.z, v.w, h1, l1);
    *(uint2*)hi = make_uint2(h0, h1);
    *(uint2*)lo = make_uint2(l0, l1);
}

// ---------------- Kernel 1: HMMA projection + fused softmax + split --------
// CTA tile 128m x 64n, K staged 64, double buffer; 48KB/stage -> 2 CTA/SM.
// Stage layout: Ahi(16K) | Alo(16K) | Bhi(8K) | Blo(8K); stage stride 48K.
#define PROJ_STAGE  49152
#define PROJ_SMEM_BYTES (2 * PROJ_STAGE)
__global__ __launch_bounds__(256, 2) void proj_mma()
{
    extern __shared__ char smem[];
    uint32_t smem_base = smem_u32(smem);
    const int tid = threadIdx.x, wid = tid >> 5, lane = tid & 31;
    const int n0 = blockIdx.x * 64, m0 = blockIdx.y * 128, gz = blockIdx.z;
    const size_t a_row0 = (size_t)(gz == 0 ? 0 : MROWS) + m0;
    const __nv_bfloat16* Whi = g_Whi + (size_t)gz * DIMM * DIMM;
    const __nv_bfloat16* Wlo = g_Wlo + (size_t)gz * DIMM * DIMM;
    __nv_bfloat16* Yhi = (gz == 0) ? g_Qhi : (gz == 1 ? g_Khi : g_Vhi);
    __nv_bfloat16* Ylo = (gz == 0) ? g_Qlo : (gz == 1 ? g_Klo : g_Vlo);

    const int lrow = tid >> 3, lseg = tid & 7;       // lrow 0..31
    const int m_base = (wid >> 1) * 32;              // 4 m-warps
    const int n_base = (wid & 1) * 32;               // 2 n-warps

    float acc[2][4][4] = {};                         // [mfrag][nfrag][reg]

    auto load_stage = [&](int kc) {
        const uint32_t stg = smem_base + (uint32_t)(kc & 1) * PROJ_STAGE;
        #pragma unroll
        for (int r = 0; r < 4; r++) {                // A: 128 rows
            int row = lrow + r * 32;
            uint32_t sw = SW128((uint32_t)(row * 128 + lseg * 16));
            size_t ga = (a_row0 + row) * DIMM + (size_t)kc * 64 + lseg * 8;
            cp_async16(stg + sw,          g_Xhi + ga);
            cp_async16(stg + 16384 + sw,  g_Xlo + ga);
        }
        #pragma unroll
        for (int r = 0; r < 2; r++) {                // B: 64 rows
            int row = lrow + r * 32;
            uint32_t sw = SW128((uint32_t)(row * 128 + lseg * 16));
            size_t gb = (size_t)(n0 + row) * DIMM + (size_t)kc * 64 + lseg * 8;
            cp_async16(stg + 32768 + sw,  Whi + gb);
            cp_async16(stg + 40960 + sw,  Wlo + gb);
        }
        CP_COMMIT();
    };

    load_stage(0);
    for (int kc = 0; kc < 8; kc++) {
        if (kc < 7) { load_stage(kc + 1); CP_WAIT(1); }
        else        { CP_WAIT(0); }
        __syncthreads();
        const uint32_t stg = smem_base + (uint32_t)(kc & 1) * PROJ_STAGE;

        #pragma unroll
        for (int t = 0; t < 4; t++) {
            const int kbyte = t * 32;
            uint32_t ahi[2][4], alo[2][4];
            #pragma unroll
            for (int f = 0; f < 2; f++) {
                uint32_t boff = (uint32_t)((m_base + f * 16 + (lane & 15)) * 128
                               + kbyte + ((lane >> 4) * 16));
                uint32_t sw = SW128(boff);
                ldmx4(stg + sw, ahi[f]);
                ldmx4(stg + 16384 + sw, alo[f]);
            }
            uint32_t bhi[4][2], blo[4][2];
            #pragma unroll
            for (int p = 0; p < 2; p++) {
                int row = n_base + p * 16 + (lane & 7) + ((lane & 16) >> 1);
                uint32_t boff = (uint32_t)(row * 128 + kbyte + (lane & 8) * 2);
                uint32_t sw = SW128(boff);
                uint32_t rh[4], rl[4];
                ldmx4(stg + 32768 + sw, rh);
                ldmx4(stg + 40960 + sw, rl);
                bhi[p*2][0] = rh[0]; bhi[p*2][1] = rh[1];
                bhi[p*2+1][0] = rh[2]; bhi[p*2+1][1] = rh[3];
                blo[p*2][0] = rl[0]; blo[p*2][1] = rl[1];
                blo[p*2+1][0] = rl[2]; blo[p*2+1][1] = rl[3];
            }
            #pragma unroll
            for (int f = 0; f < 2; f++)
                #pragma unroll
                for (int nf = 0; nf < 4; nf++) {
                    mma16816(acc[f][nf], ahi[f], bhi[nf]);
                    mma16816(acc[f][nf], ahi[f], blo[nf]);
                    mma16816(acc[f][nf], alo[f], bhi[nf]);
                }
        }
        __syncthreads();
    }

    // fused softmax: warp's 32 cols = exactly one 32-col head group
    if (gz < 2) {
        #pragma unroll
        for (int f = 0; f < 2; f++) {
            float mx0 = -1e30f, mx1 = -1e30f;
            #pragma unroll
            for (int nf = 0; nf < 4; nf++) {
                mx0 = fmaxf(mx0, fmaxf(acc[f][nf][0], acc[f][nf][1]));
                mx1 = fmaxf(mx1, fmaxf(acc[f][nf][2], acc[f][nf][3]));
            }
            mx0 = fmaxf(mx0, __shfl_xor_sync(~0u, mx0, 1));
            mx0 = fmaxf(mx0, __shfl_xor_sync(~0u, mx0, 2));
            mx1 = fmaxf(mx1, __shfl_xor_sync(~0u, mx1, 1));
            mx1 = fmaxf(mx1, __shfl_xor_sync(~0u, mx1, 2));
            float s0 = 0.f, s1 = 0.f;
            #pragma unroll
            for (int nf = 0; nf < 4; nf++) {
                acc[f][nf][0] = __expf(acc[f][nf][0] - mx0);
                acc[f][nf][1] = __expf(acc[f][nf][1] - mx0);
                acc[f][nf][2] = __expf(acc[f][nf][2] - mx1);
                acc[f][nf][3] = __expf(acc[f][nf][3] - mx1);
                s0 += acc[f][nf][0] + acc[f][nf][1];
                s1 += acc[f][nf][2] + acc[f][nf][3];
            }
            s0 += __shfl_xor_sync(~0u, s0, 1);
            s0 += __shfl_xor_sync(~0u, s0, 2);
            s1 += __shfl_xor_sync(~0u, s1, 1);
            s1 += __shfl_xor_sync(~0u, s1, 2);
            float r0 = 1.f / s0, r1 = 1.f / s1;
            #pragma unroll
            for (int nf = 0; nf < 4; nf++) {
                acc[f][nf][0] *= r0; acc[f][nf][1] *= r0;
                acc[f][nf][2] *= r1; acc[f][nf][3] *= r1;
            }
        }
    }

    // split to bf16 hi/lo and store
    const int r0 = lane >> 2, c0 = (lane & 3) * 2;
    #pragma unroll
    for (int f = 0; f < 2; f++) {
        int row = m0 + m_base + f * 16 + r0;
        #pragma unroll
        for (int nf = 0; nf < 4; nf++) {
            int col = n0 + n_base + nf * 8 + c0;
            uint32_t h, l;
            split2(acc[f][nf][0], acc[f][nf][1], h, l);
            *(uint32_t*)&Yhi[(size_t)row * DIMM + col] = h;
            *(uint32_t*)&Ylo[(size_t)row * DIMM + col] = l;
            split2(acc[f][nf][2], acc[f][nf][3], h, l);
            *(uint32_t*)&Yhi[(size_t)(row + 8) * DIMM + col] = h;
            *(uint32_t*)&Ylo[(size_t)(row + 8) * DIMM + col] = l;
        }
    }
}

// ---------------- Kernel 3: HMMA chunk sums CS = K^T V ---------------------
#define TS 80   // smem row stride bytes (64B data + 16 pad)
__global__ __launch_bounds__(64) void chunk_sum()
{
    __shared__ char sm[4 * 128 * TS];
    uint32_t sb = smem_u32(sm);
    const uint32_t Khi_s = sb, Klo_s = sb + 128*TS, Vhi_s = sb + 2*128*TS, Vlo_s = sb + 3*128*TS;
    const int c = blockIdx.x, h = blockIdx.y, n = blockIdx.z;
    const int tid = threadIdx.x, w = tid >> 5, lane = tid & 31;
    const size_t base = ((size_t)(n * LSEQ + c * TCH)) * DIMM + h * DD;

    #pragma unroll
    for (int r = 0; r < 8; r++) {
        int idx = tid + r * 64;
        int row = idx >> 2, seg = idx & 3;
        size_t g = base + (size_t)row * DIMM + seg * 8;
        uint32_t so = (uint32_t)(row * TS + seg * 16);
        *(uint4*)(sm + 0*128*TS + so) = *(const uint4*)(g_Khi + g);
        *(uint4*)(sm + 1*128*TS + so) = *(const uint4*)(g_Klo + g);
        *(uint4*)(sm + 2*128*TS + so) = *(const uint4*)(g_Vhi + g);
        *(uint4*)(sm + 3*128*TS + so) = *(const uint4*)(g_Vlo + g);
    }
    __syncthreads();

    const int m0 = w * 16;
    float acc[4][4] = {};
    const uint32_t a_off = (uint32_t)(((lane & 7) + ((lane >> 4) << 3)) * TS
                         + (m0 + ((lane >> 3) & 1) * 8) * 2);
    const uint32_t b_off = (uint32_t)((lane & 15) * TS + ((lane >> 4) * 8) * 2);

    #pragma unroll
    for (int kk = 0; kk < 8; kk++) {
        const uint32_t krow = (uint32_t)(kk * 16) * TS;
        uint32_t ahi[4], alo[4];
        ldmx4t(Khi_s + krow + a_off, ahi);
        ldmx4t(Klo_s + krow + a_off, alo);
        #pragma unroll
        for (int q = 0; q < 2; q++) {
            uint32_t bh[4], bl[4];
            ldmx4t(Vhi_s + krow + b_off + q * 32, bh);
            ldmx4t(Vlo_s + krow + b_off + q * 32, bl);
            #pragma unroll
            for (int s = 0; s < 2; s++) {
                int nf = q * 2 + s;
                mma16816(acc[nf], ahi, bh + s * 2);
                mma16816(acc[nf], ahi, bl + s * 2);
                mma16816(acc[nf], alo, bh + s * 2);
            }
        }
    }
    size_t ob = ((size_t)((n * HH + h) * CCH + c)) * 1024;
    const int dr = m0 + (lane >> 2), ec = (lane & 3) * 2;
    #pragma unroll
    for (int nf = 0; nf < 4; nf++) {
        *(float2*)&g_CS[ob + (size_t)dr * 32 + nf * 8 + ec] = make_float2(acc[nf][0], acc[nf][1]);
        *(float2*)&g_CS[ob + (size_t)(dr + 8) * 32 + nf * 8 + ec] = make_float2(acc[nf][2], acc[nf][3]);
    }
}

// ---------------- Kernel 4: exclusive prefix over chunks ------------------
__global__ __launch_bounds__(1024) void prefix_state()
{
    const int bh = blockIdx.x;
    const int tid = threadIdx.x;
    float acc = 0.f;
    size_t base = (size_t)bh * CCH * 1024 + tid;
    #pragma unroll
    for (int c = 0; c < CCH; c++) {
        g_S0[base + (size_t)c * 1024] = acc;
        acc += g_CS[base + (size_t)c * 1024];
    }
}

// ---------------- Kernel 5: HMMA intra-chunk causal attention --------------
#define ATTN_SMEM_BYTES (6*128*TS + 2*32*TS)
__global__ __launch_bounds__(256) void chunk_attn(float* __restrict__ out)
{
    extern __shared__ char sm[];
    uint32_t sb = smem_u32(sm);
    const uint32_t Qhi_s = sb,            Qlo_s = sb + 128*TS;
    const uint32_t Khi_s = sb + 2*128*TS, Klo_s = sb + 3*128*TS;
    const uint32_t Vhi_s = sb + 4*128*TS, Vlo_s = sb + 5*128*TS;
    const uint32_t Shi_s = sb + 6*128*TS, Slo_s = sb + 6*128*TS + 32*TS;

    const int c = blockIdx.x, h = blockIdx.y, n = blockIdx.z;
    const int tid = threadIdx.x, wid = tid >> 5, lane = tid & 31;
    const size_t base = ((size_t)(n * LSEQ + c * TCH)) * DIMM + h * DD;

    #pragma unroll
    for (int r = 0; r < 2; r++) {
        int idx = tid + r * 256;
        int row = idx >> 2, seg = idx & 3;
        size_t g = base + (size_t)row * DIMM + seg * 8;
        uint32_t so = (uint32_t)(row * TS + seg * 16);
        *(uint4*)(sm + 0*128*TS + so) = *(const uint4*)(g_Qhi + g);
        *(uint4*)(sm + 1*128*TS + so) = *(const uint4*)(g_Qlo + g);
        *(uint4*)(sm + 2*128*TS + so) = *(const uint4*)(g_Khi + g);
        *(uint4*)(sm + 3*128*TS + so) = *(const uint4*)(g_Klo + g);
        *(uint4*)(sm + 4*128*TS + so) = *(const uint4*)(g_Vhi + g);
        *(uint4*)(sm + 5*128*TS + so) = *(const uint4*)(g_Vlo + g);
    }
    {
        size_t sbase = ((size_t)((n * HH + h) * CCH + c)) * 1024;
        int d = tid >> 3, e0 = (tid & 7) * 4;
        float4 v = *(const float4*)&g_S0[sbase + (size_t)d * 32 + e0];
        uint32_t h0, l0, h1, l1;
        split2(v.x, v.y, h0, l0);
        split2(v.z, v.w, h1, l1);
        uint32_t so = (uint32_t)(d * TS + e0 * 2);
        *(uint2*)(sm + 6*128*TS + so)         = make_uint2(h0, h1);
        *(uint2*)(sm + 6*128*TS + 32*TS + so) = make_uint2(l0, l1);
    }
    __syncthreads();

    const int m_base = wid * 16;

    uint32_t qhi[2][4], qlo[2][4];
    {
        uint32_t a_off = (uint32_t)((m_base + (lane & 15)) * TS + (lane >> 4) * 16);
        #pragma unroll
        for (int kk = 0; kk < 2; kk++) {
            ldmx4(Qhi_s + a_off + kk * 32, qhi[kk]);
            ldmx4(Qlo_s + a_off + kk * 32, qlo[kk]);
        }
    }
    float A[16][4] = {};
    {
        const uint32_t b_base = (uint32_t)(((lane & 7) + ((lane & 16) >> 1)) * TS + (lane & 8) * 2);
        #pragma unroll
        for (int kk = 0; kk < 2; kk++) {
            #pragma unroll
            for (int p = 0; p < 8; p++) {
                uint32_t off = b_base + (uint32_t)(p * 16) * TS + kk * 32;
                uint32_t bh[4], bl[4];
                ldmx4(Khi_s + off, bh);
                ldmx4(Klo_s + off, bl);
                #pragma unroll
                for (int s = 0; s < 2; s++) {
                    int nf = p * 2 + s;
                    mma16816(A[nf], qhi[kk], bh + s * 2);
                    mma16816(A[nf], qhi[kk], bl + s * 2);
                    mma16816(A[nf], qlo[kk], bh + s * 2);
                }
            }
        }
    }
    {
        const int i0 = m_base + (lane >> 2), i1 = i0 + 8;
        const int jb = (lane & 3) * 2;
        #pragma unroll
        for (int nf = 0; nf < 16; nf++) {
            int j0 = nf * 8 + jb;
            if (j0     > i0) A[nf][0] = 0.f;
            if (j0 + 1 > i0) A[nf][1] = 0.f;
            if (j0     > i1) A[nf][2] = 0.f;
            if (j0 + 1 > i1) A[nf][3] = 0.f;
        }
    }

    float o[4][4] = {};
    const uint32_t bt_off = (uint32_t)((lane & 15) * TS + ((lane >> 4) * 8) * 2);
    #pragma unroll
    for (int kk = 0; kk < 8; kk++) {
        uint32_t ahi[4], alo[4];
        split2(A[2*kk][0],   A[2*kk][1],   ahi[0], alo[0]);
        split2(A[2*kk][2],   A[2*kk][3],   ahi[1], alo[1]);
        split2(A[2*kk+1][0], A[2*kk+1][1], ahi[2], alo[2]);
        split2(A[2*kk+1][2], A[2*kk+1][3], ahi[3], alo[3]);
        const uint32_t krow = (uint32_t)(kk * 16) * TS;
        #pragma unroll
        for (int q = 0; q < 2; q++) {
            uint32_t bh[4], bl[4];
            ldmx4t(Vhi_s + krow + bt_off + q * 32, bh);
            ldmx4t(Vlo_s + krow + bt_off + q * 32, bl);
            #pragma unroll
            for (int s = 0; s < 2; s++) {
                int nf = q * 2 + s;
                mma16816(o[nf], ahi, bh + s * 2);
                mma16816(o[nf], ahi, bl + s * 2);
                mma16816(o[nf], alo, bh + s * 2);
            }
        }
    }
    #pragma unroll
    for (int kk = 0; kk < 2; kk++) {
        const uint32_t krow = (uint32_t)(kk * 16) * TS;
        #pragma unroll
        for (int q = 0; q < 2; q++) {
            uint32_t bh[4], bl[4];
            ldmx4t(Shi_s + krow + bt_off + q * 32, bh);
            ldmx4t(Slo_s + krow + bt_off + q * 32, bl);
            #pragma unroll
            for (int s = 0; s < 2; s++) {
                int nf = q * 2 + s;
                mma16816(o[nf], qhi[kk], bh + s * 2);
                mma16816(o[nf], qhi[kk], bl + s * 2);
                mma16816(o[nf], qlo[kk], bh + s * 2);
            }
        }
    }

    const int r0 = lane >> 2, ec = (lane & 3) * 2;
    #pragma unroll
    for (int nf = 0; nf < 4; nf++) {
        size_t p0 = base + (size_t)(m_base + r0) * DIMM + nf * 8 + ec;
        *(float2*)&out[p0]              = make_float2(o[nf][0], o[nf][1]);
        *(float2*)&out[p0 + 8 * DIMM]   = make_float2(o[nf][2], o[nf][3]);
    }
}

// ---------------- launch ---------------------------------------------------
extern "C" void kernel_launch(void* const* d_in, const int* in_sizes, int n_in,
                              void* d_out, int out_size)
{
    const float* query = (const float*)d_in[0];
    const float* key   = (const float*)d_in[1];
    const float* Wq    = (const float*)d_in[2];
    const float* Wk    = (const float*)d_in[3];
    const float* Wv    = (const float*)d_in[4];
    float* out = (float*)d_out;

    cudaFuncSetAttribute(proj_mma, cudaFuncAttributeMaxDynamicSharedMemorySize,
                         PROJ_SMEM_BYTES);
    cudaFuncSetAttribute(chunk_attn, cudaFuncAttributeMaxDynamicSharedMemorySize,
                         ATTN_SMEM_BYTES);

    // 0) split fp32 -> bf16 hi/lo (X and W)
    {
        const size_t XQ = (size_t)2 * MROWS * DIMM / 4;
        const size_t WQ = (size_t)DIMM * DIMM / 4;
        int blocks = (int)((XQ + 3 * WQ + 255) / 256);
        split_bf16<<<blocks, 256>>>(query, key, Wq, Wk, Wv);
    }
    // 1) projections + fused softmax + bf16 hi/lo output (128x64 tiles, occ 2)
    proj_mma<<<dim3(DIMM / 64, MROWS / 128, 3), 256, PROJ_SMEM_BYTES>>>();
    // 2) per-chunk K^T V sums (HMMA)
    chunk_sum<<<dim3(CCH, HH, NB), 64>>>();
    // 3) exclusive prefix of chunk states
    prefix_state<<<NB * HH, 1024>>>();
    // 4) intra-chunk causal attention + output (HMMA)
    chunk_attn<<<dim3(CCH, HH, NB), 256, ATTN_SMEM_BYTES>>>(out);
}